// round 11
// baseline (speedup 1.0000x reference)
#include <cuda_runtime.h>
#include <cuda_fp16.h>
#include <cstdint>
#include <cstddef>

// ---------------- problem constants ----------------
namespace {
constexpr int kT = 8192, kD = 2048, kF = 4096, kE = 8;
constexpr int TMm = 128;                 // CTA tile M
constexpr int TN  = 128;                 // CTA tile N
constexpr int ROWT = kT / TMm + kE;      // 72 padded row tiles max
constexpr int TPAD = ROWT * TMm;         // 9216
constexpr int BK = 64;                   // halves per K chunk (128 B rows)
constexpr int ST = 3;                    // pipeline stages
constexpr int A_BYTES = TMm * BK * 2;    // 16 KB
constexpr int B_BYTES = TN * BK * 2;     // 16 KB
constexpr int STG = A_BYTES + B_BYTES;   // 32 KB
constexpr int SMEM_BYTES = ST * STG;     // 96 KB  -> 2 CTAs/SM
constexpr int NTH = 256;                 // 8 warps (2M x 4N), warp tile 64x32
// w2 conversion folded into GEMM1 grid (gridDim.x = kF/TN = 32)
constexpr int CVTY = 16;                 // 16 interleaved y-slices (x32 CTAs)
constexpr int CVT_THREADS = CVTY * 32 * NTH;          // 131072
constexpr long long W2_N8 = ((long long)kE * kD * kF) / 8;   // 8388608 uint4
constexpr long long W1_N8 = ((long long)kE * kF * kD) / 8;   // 8388608 uint4
constexpr int G1Y = ROWT + CVTY;          // 88 total y for GEMM1 (+cvt)
constexpr int G1Y_A = 44;                 // first half launch
}

// ---------------- scratch globals ----------------
__device__ int g_counts[kE];
__device__ int g_cursor[kE];
__device__ int g_rowtoken[TPAD];
__device__ int g_tile_expert[ROWT];
__device__ __half g_xperm[(size_t)TPAD * kD];     // permuted+padded fp16 tokens
__device__ __half g_w1h[(size_t)kE * kF * kD];
__device__ __half g_w2h[(size_t)kE * kD * kF];
__device__ __half g_h1h[(size_t)TPAD * kF];       // silu(x@w1^T) fp16

// ---------------- helpers ----------------
__device__ __forceinline__ uint32_t smem_u32(const void* p) {
    uint32_t a;
    asm("{ .reg .u64 t; cvta.to.shared.u64 t, %1; cvt.u32.u64 %0, t; }" : "=r"(a) : "l"(p));
    return a;
}
__device__ __forceinline__ void ldsm_x4(uint32_t* r, uint32_t addr) {
    asm volatile("ldmatrix.sync.aligned.m8n8.x4.shared.b16 {%0,%1,%2,%3}, [%4];"
                 : "=r"(r[0]), "=r"(r[1]), "=r"(r[2]), "=r"(r[3]) : "r"(addr));
}
__device__ __forceinline__ void mma_f16(float* c, const uint32_t* a, uint32_t b0, uint32_t b1) {
    asm volatile(
        "mma.sync.aligned.m16n8k16.row.col.f32.f16.f16.f32 "
        "{%0,%1,%2,%3}, {%4,%5,%6,%7}, {%8,%9}, {%0,%1,%2,%3};\n"
        : "+f"(c[0]), "+f"(c[1]), "+f"(c[2]), "+f"(c[3])
        : "r"(a[0]), "r"(a[1]), "r"(a[2]), "r"(a[3]), "r"(b0), "r"(b1));
}
__device__ __forceinline__ void cp_async16(uint32_t dst, const void* src) {
    asm volatile("cp.async.cg.shared.global [%0], [%1], 16;" :: "r"(dst), "l"(src));
}
__device__ __forceinline__ void cvt8(const float4* __restrict__ s, uint4* __restrict__ d) {
    float4 a = s[0], b = s[1];
    __half2 h0 = __floats2half2_rn(a.x, a.y), h1 = __floats2half2_rn(a.z, a.w);
    __half2 h2 = __floats2half2_rn(b.x, b.y), h3 = __floats2half2_rn(b.z, b.w);
    uint4 o;
    o.x = *(uint32_t*)&h0; o.y = *(uint32_t*)&h1;
    o.z = *(uint32_t*)&h2; o.w = *(uint32_t*)&h3;
    *d = o;
}

// ---------------- routing ----------------
// (1) per-token argmax only (no atomics, no pre-zero ordering hazard)
__global__ void k_route(const float* __restrict__ logits) {
    int t = blockIdx.x * blockDim.x + threadIdx.x;
    if (t >= kT) return;
    const float* l = logits + (size_t)t * kE;
    int best = 0; float bv = l[0];
#pragma unroll
    for (int e = 1; e < kE; e++) { float v = l[e]; if (v > bv) { bv = v; best = e; } }
    ((int*)g_xperm)[t] = best;     // temp storage, overwritten by k_prep later
}
// (2) single block: count assigns, build offsets + tile map, init rowtoken
__global__ void k_offsets() {
    __shared__ int sc[kE];
    if (threadIdx.x < kE) sc[threadIdx.x] = 0;
    __syncthreads();
    for (int t = threadIdx.x; t < kT; t += blockDim.x)
        atomicAdd(&sc[((int*)g_xperm)[t]], 1);
    __syncthreads();
    if (threadIdx.x == 0) {
        int off = 0;
        for (int e = 0; e < kE; e++) {
            g_counts[e] = sc[e];
            g_cursor[e] = off;
            int nt = (sc[e] + TMm - 1) / TMm;
            for (int i = 0; i < nt; i++) g_tile_expert[off / TMm + i] = e;
            off += nt * TMm;
        }
        for (int rt = off / TMm; rt < ROWT; rt++) g_tile_expert[rt] = -1;
    }
    for (int i = threadIdx.x; i < TPAD; i += blockDim.x) g_rowtoken[i] = -1;
}
// (3) scatter tokens into padded expert-contiguous order
__global__ void k_scatter() {
    int t = blockIdx.x * blockDim.x + threadIdx.x;
    if (t >= kT) return;
    int e = ((int*)g_xperm)[t];
    int pos = atomicAdd(&g_cursor[e], 1);
    g_rowtoken[pos] = t;
}
// (4) merged: w1 fp32->fp16 + token gather/convert/zero-pad (one DRAM pass)
__global__ void k_prep(const float4* __restrict__ w1, const float4* __restrict__ hs) {
    long long i = (long long)blockIdx.x * blockDim.x + threadIdx.x;
    if (i < W1_N8) cvt8(w1 + 2 * (size_t)i, ((uint4*)g_w1h) + i);
    if (i < (long long)TPAD * 256) {
        int row = (int)(i >> 8);
        int q = (int)(i & 255);
        int tok = g_rowtoken[row];
        uint4 o = make_uint4(0, 0, 0, 0);
        if (tok >= 0) {
            const float4* s = hs + (size_t)tok * (kD / 4) + 2 * q;
            float4 a = s[0], b = s[1];
            __half2 h0 = __floats2half2_rn(a.x, a.y), h1 = __floats2half2_rn(a.z, a.w);
            __half2 h2 = __floats2half2_rn(b.x, b.y), h3 = __floats2half2_rn(b.z, b.w);
            o.x = *(uint32_t*)&h0; o.y = *(uint32_t*)&h1;
            o.z = *(uint32_t*)&h2; o.w = *(uint32_t*)&h3;
        }
        ((uint4*)g_xperm)[i] = o;
    }
}

// ---------------- fp16 HMMA GEMM -----------------------------------------
// CTA tile 128x128, 8 warps (2 M x 4 N), warp tile 64x32, occupancy 2
// => 16 warps/SM = 4 warps/SMSP (cross-CTA latency hiding).
// 3-stage cp.async pipeline, 1 barrier/chunk, tail-correct waits.
// FIRST:  h1[TPAD,kF] = silu(g_xperm @ w1[e]^T); w2 fp16 conversion CTAs folded in.
// !FIRST: out[tok,kD] = g_h1h @ w2[e]^T   (scatter; pad rows dropped)
template <bool FIRST>
__global__ __launch_bounds__(NTH, 2) void k_gemm(const float4* __restrict__ w2src,
                                                 float* __restrict__ out, int ybase)
{
    constexpr int N = FIRST ? kF : kD;
    constexpr int K = FIRST ? kD : kF;
    constexpr int NC = K / BK;

    int rt;
    if (FIRST) {
        // interleaved role mapping over absolute y: y%3==2 && y<48 -> w2 cvt slice
        const int y = blockIdx.y + ybase;
        if (y < 3 * CVTY && (y % 3) == 2) {
            const int slice = y / 3;
            long long base = ((long long)(slice * 32 + blockIdx.x) * NTH + threadIdx.x);
            uint4* dst = (uint4*)g_w2h;
#pragma unroll 4
            for (long long i = base; i < W2_N8; i += CVT_THREADS)
                cvt8(w2src + 2 * (size_t)i, dst + i);
            return;
        }
        rt = (y < 3 * CVTY) ? (y - (y + 1) / 3) : (y - CVTY);
    } else {
        rt = blockIdx.y;
    }

    const int e = g_tile_expert[rt];
    if (e < 0) return;
    const int rowbase = rt * TMm;
    const int colbase = blockIdx.x * TN;

    extern __shared__ char smem[];
    const uint32_t sb = smem_u32(smem);
    const int tid = threadIdx.x;
    const int warp = tid >> 5, lane = tid & 31;
    const int wm = warp & 1, wn = warp >> 1;   // 2 x 4 warps, 64x32 each

    const __half* Abase = FIRST ? g_xperm : g_h1h;
    const __half* Wb = (FIRST ? g_w1h : g_w2h) + (size_t)e * ((size_t)N * K);

    // ---- cp.async mapping: q = 16B group along K, r = base row (0..31) ----
    const int q = tid & 7, r = tid >> 3;
    const __half* aptr = Abase + (size_t)(rowbase + r) * K + q * 8;
    const __half* bptr = Wb + (size_t)(colbase + r) * K + q * 8;
    const uint32_t dA = (uint32_t)(r * 128 + ((q ^ (r & 7)) << 4));  // p*32 preserves row&7

    auto prefetch = [&](int c) {
        const uint32_t base = sb + (uint32_t)((c % ST) * STG);
        const __half* ap = aptr + c * BK;
#pragma unroll
        for (int p = 0; p < 4; p++)
            cp_async16(base + dA + (uint32_t)(p * 32 * 128), ap + (size_t)p * 32 * K);
        const __half* bp = bptr + c * BK;
#pragma unroll
        for (int p = 0; p < 4; p++)
            cp_async16(base + A_BYTES + dA + (uint32_t)(p * 32 * 128), bp + (size_t)p * 32 * K);
        asm volatile("cp.async.commit_group;" ::: "memory");
    };

    prefetch(0);
    prefetch(1);

    // ---- ldmatrix lane geometry ----
    const int rowA = wm * 64 + (lane & 15);          // A: 4 x (16m x 16k) frags
    const int kgA = lane >> 4;
    const int rowB = wn * 32 + ((lane >> 4) << 3) + (lane & 7);  // B: 2 x (16n x 16k)
    const int kgB = (lane >> 3) & 1;

    float acc[4][4][4];
#pragma unroll
    for (int i = 0; i < 4; i++)
#pragma unroll
        for (int j = 0; j < 4; j++)
#pragma unroll
            for (int v = 0; v < 4; v++) acc[i][j][v] = 0.f;

    for (int c = 0; c < NC; c++) {
        // tail-correct wait: group c must be complete before reading its stage
        if (c < NC - 1) asm volatile("cp.async.wait_group 1;" ::: "memory");
        else            asm volatile("cp.async.wait_group 0;" ::: "memory");
        __syncthreads();                        // single barrier per chunk
        if (c + 2 < NC) prefetch(c + 2);

        const uint32_t stA = sb + (uint32_t)((c % ST) * STG);
        const uint32_t stB = stA + A_BYTES;
#pragma unroll
        for (int s = 0; s < 4; s++) {           // 4 k16-steps
            uint32_t a[4][4];
#pragma unroll
            for (int mi = 0; mi < 4; mi++) {
                const int rr = rowA + mi * 16;
                ldsm_x4(a[mi], stA + (uint32_t)(rr * 128 + (((2 * s + kgA) ^ (rr & 7)) << 4)));
            }
            uint32_t b[2][4];
#pragma unroll
            for (int nj2 = 0; nj2 < 2; nj2++) {
                const int rr = rowB + nj2 * 16;
                ldsm_x4(b[nj2], stB + (uint32_t)(rr * 128 + (((2 * s + kgB) ^ (rr & 7)) << 4)));
            }
#pragma unroll
            for (int mi = 0; mi < 4; mi++)
#pragma unroll
                for (int nj = 0; nj < 4; nj++)
                    mma_f16(acc[mi][nj], a[mi], b[nj >> 1][(nj & 1) * 2], b[nj >> 1][(nj & 1) * 2 + 1]);
        }
    }

    // ---- epilogue (warp covers 64m x 32n) ----
    const int g = lane >> 2, tig = lane & 3;
#pragma unroll
    for (int mi = 0; mi < 4; mi++) {
#pragma unroll
        for (int rr = 0; rr < 2; rr++) {
            const int lrow = rowbase + wm * 64 + mi * 16 + g + rr * 8;
            if (FIRST) {
                __half* hp = g_h1h + (size_t)lrow * kF + colbase;
#pragma unroll
                for (int nj = 0; nj < 4; nj++) {
                    const int col = wn * 32 + nj * 8 + tig * 2;
                    float v0 = acc[mi][nj][rr * 2 + 0];
                    float v1 = acc[mi][nj][rr * 2 + 1];
                    v0 = v0 / (1.f + __expf(-v0));       // SiLU
                    v1 = v1 / (1.f + __expf(-v1));
                    __half2 h = __floats2half2_rn(v0, v1);
                    *(uint32_t*)(hp + col) = *(uint32_t*)&h;
                }
            } else {
                const int tok = g_rowtoken[lrow];
                if (tok >= 0) {
                    float* op = out + (size_t)tok * kD + colbase;
#pragma unroll
                    for (int nj = 0; nj < 4; nj++) {
                        const int col = wn * 32 + nj * 8 + tig * 2;
                        float2 st;
                        st.x = acc[mi][nj][rr * 2 + 0];
                        st.y = acc[mi][nj][rr * 2 + 1];
                        *(float2*)(op + col) = st;
                    }
                }
            }
        }
    }
}

// ---------------- entry ----------------
extern "C" void kernel_launch(void* const* d_in, const int* in_sizes, int n_in,
                              void* d_out, int out_size) {
    const float* hs     = (const float*)d_in[0];
    const float* logits = (const float*)d_in[1];
    const float* w1     = (const float*)d_in[2];
    const float* w2     = (const float*)d_in[3];
    float* out = (float*)d_out;

    cudaFuncSetAttribute(k_gemm<true>,  cudaFuncAttributeMaxDynamicSharedMemorySize, SMEM_BYTES);
    cudaFuncSetAttribute(k_gemm<false>, cudaFuncAttributeMaxDynamicSharedMemorySize, SMEM_BYTES);

    // #1-#3: routing
    k_route<<<kT / 256, 256>>>(logits);
    k_offsets<<<1, 256>>>();
    k_scatter<<<kT / 256, 256>>>();
    // #4: w1 cvt + token permute (one DRAM pass)
    k_prep<<<(unsigned)((W1_N8 + 255) / 256), 256>>>((const float4*)w1, (const float4*)hs);

    // #5 + #6: GEMM1 in two halves (w2-conversion CTAs folded in), for ncu visibility
    dim3 g1a(kF / TN, G1Y_A);
    k_gemm<true><<<g1a, NTH, SMEM_BYTES>>>((const float4*)w2, nullptr, 0);
    dim3 g1b(kF / TN, G1Y - G1Y_A);
    k_gemm<true><<<g1b, NTH, SMEM_BYTES>>>((const float4*)w2, nullptr, G1Y_A);
    // #7: GEMM2
    dim3 g2(kD / TN, ROWT);
    k_gemm<false><<<g2, NTH, SMEM_BYTES>>>(nullptr, out, 0);
}

// round 12
// speedup vs baseline: 1.0470x; 1.0470x over previous
#include <cuda_runtime.h>
#include <cuda_fp16.h>
#include <cstdint>
#include <cstddef>

// ---------------- problem constants ----------------
namespace {
constexpr int kT = 8192, kD = 2048, kF = 4096, kE = 8;
constexpr int TMm = 128;                 // CTA tile M
constexpr int TN  = 128;                 // CTA tile N
constexpr int ROWT = kT / TMm + kE;      // 72 padded row tiles max
constexpr int TPAD = ROWT * TMm;         // 9216
constexpr int BK = 64;                   // halves per K chunk (128 B rows)
constexpr int ST = 3;                    // pipeline stages
constexpr int A_BYTES = TMm * BK * 2;    // 16 KB
constexpr int B_BYTES = TN * BK * 2;     // 16 KB
constexpr int STG = A_BYTES + B_BYTES;   // 32 KB
constexpr int SMEM_BYTES = ST * STG;     // 96 KB  -> 2 CTAs/SM
constexpr int NTH = 128;                 // 4 warps (2M x 2N), warp tile 64x64

constexpr long long W1_N8 = ((long long)kE * kF * kD) / 8;   // 8388608 uint4
constexpr long long W2_N8 = ((long long)kE * kD * kF) / 8;   // 8388608 uint4

// fused launch schedule
constexpr int NCVT = 512;                          // w2-cvt slice CTAs
constexpr int CVT_CHUNK = (int)(W2_N8 / NCVT);     // 16384 uint4 per slice
constexpr int XT1 = kF / TN;                       // 32 GEMM1 x-tiles
constexpr int XT2 = kD / TN;                       // 16 GEMM2 x-tiles
constexpr int NT1 = XT1 * ROWT;                    // 2304 GEMM1 tiles
constexpr int NT2 = XT2 * ROWT;                    // 1152 GEMM2 tiles
constexpr int MIX = 3 * NCVT;                      // 1536 interleaved ids
constexpr int PH1 = NT1 + NCVT;                    // 2816
constexpr int TOTAL = PH1 + NT2;                   // 3968
}

// ---------------- scratch globals ----------------
__device__ int g_counts[kE];
__device__ int g_cursor[kE];
__device__ int g_rowtoken[TPAD];
__device__ int g_tile_expert[ROWT];
__device__ int g_cvtdone;                // completed w2-cvt slices
__device__ int g_done1[ROWT];            // completed GEMM1 x-tiles per rt
__device__ __half g_xperm[(size_t)TPAD * kD];     // permuted+padded fp16 tokens
__device__ __half g_w1h[(size_t)kE * kF * kD];
__device__ __half g_w2h[(size_t)kE * kD * kF];
__device__ __half g_h1h[(size_t)TPAD * kF];       // silu(x@w1^T) fp16

// ---------------- helpers ----------------
__device__ __forceinline__ uint32_t smem_u32(const void* p) {
    uint32_t a;
    asm("{ .reg .u64 t; cvta.to.shared.u64 t, %1; cvt.u32.u64 %0, t; }" : "=r"(a) : "l"(p));
    return a;
}
__device__ __forceinline__ void ldsm_x4(uint32_t* r, uint32_t addr) {
    asm volatile("ldmatrix.sync.aligned.m8n8.x4.shared.b16 {%0,%1,%2,%3}, [%4];"
                 : "=r"(r[0]), "=r"(r[1]), "=r"(r[2]), "=r"(r[3]) : "r"(addr));
}
__device__ __forceinline__ void mma_f16(float* c, const uint32_t* a, uint32_t b0, uint32_t b1) {
    asm volatile(
        "mma.sync.aligned.m16n8k16.row.col.f32.f16.f16.f32 "
        "{%0,%1,%2,%3}, {%4,%5,%6,%7}, {%8,%9}, {%0,%1,%2,%3};\n"
        : "+f"(c[0]), "+f"(c[1]), "+f"(c[2]), "+f"(c[3])
        : "r"(a[0]), "r"(a[1]), "r"(a[2]), "r"(a[3]), "r"(b0), "r"(b1));
}
__device__ __forceinline__ void cp_async16(uint32_t dst, const void* src) {
    asm volatile("cp.async.cg.shared.global [%0], [%1], 16;" :: "r"(dst), "l"(src));
}
__device__ __forceinline__ void cvt8(const float4* __restrict__ s, uint4* __restrict__ d) {
    float4 a = s[0], b = s[1];
    __half2 h0 = __floats2half2_rn(a.x, a.y), h1 = __floats2half2_rn(a.z, a.w);
    __half2 h2 = __floats2half2_rn(b.x, b.y), h3 = __floats2half2_rn(b.z, b.w);
    uint4 o;
    o.x = *(uint32_t*)&h0; o.y = *(uint32_t*)&h1;
    o.z = *(uint32_t*)&h2; o.w = *(uint32_t*)&h3;
    *d = o;
}
__device__ __forceinline__ int ld_acquire(const int* p) {
    int v;
    asm volatile("ld.acquire.gpu.global.b32 %0, [%1];" : "=r"(v) : "l"(p) : "memory");
    return v;
}

// ---------------- routing ----------------
__global__ void k_route(const float* __restrict__ logits) {
    int t = blockIdx.x * blockDim.x + threadIdx.x;
    if (t >= kT) return;
    const float* l = logits + (size_t)t * kE;
    int best = 0; float bv = l[0];
#pragma unroll
    for (int e = 1; e < kE; e++) { float v = l[e]; if (v > bv) { bv = v; best = e; } }
    ((int*)g_xperm)[t] = best;     // temp storage, overwritten by k_prep later
}
// single block: count assigns, offsets, tile map, init rowtoken + sync counters
__global__ void k_offsets() {
    __shared__ int sc[kE];
    if (threadIdx.x < kE) sc[threadIdx.x] = 0;
    __syncthreads();
    for (int t = threadIdx.x; t < kT; t += blockDim.x)
        atomicAdd(&sc[((int*)g_xperm)[t]], 1);
    __syncthreads();
    if (threadIdx.x == 0) {
        int off = 0;
        for (int e = 0; e < kE; e++) {
            g_counts[e] = sc[e];
            g_cursor[e] = off;
            int nt = (sc[e] + TMm - 1) / TMm;
            for (int i = 0; i < nt; i++) g_tile_expert[off / TMm + i] = e;
            off += nt * TMm;
        }
        for (int rt = off / TMm; rt < ROWT; rt++) g_tile_expert[rt] = -1;
        g_cvtdone = 0;
    }
    for (int i = threadIdx.x; i < TPAD; i += blockDim.x) g_rowtoken[i] = -1;
    for (int i = threadIdx.x; i < ROWT; i += blockDim.x) g_done1[i] = 0;
}
__global__ void k_scatter() {
    int t = blockIdx.x * blockDim.x + threadIdx.x;
    if (t >= kT) return;
    int e = ((int*)g_xperm)[t];
    int pos = atomicAdd(&g_cursor[e], 1);
    g_rowtoken[pos] = t;
}
// merged: w1 fp32->fp16 + token gather/convert/zero-pad (one DRAM pass)
__global__ void k_prep(const float4* __restrict__ w1, const float4* __restrict__ hs) {
    long long i = (long long)blockIdx.x * blockDim.x + threadIdx.x;
    if (i < W1_N8) cvt8(w1 + 2 * (size_t)i, ((uint4*)g_w1h) + i);
    if (i < (long long)TPAD * 256) {
        int row = (int)(i >> 8);
        int q = (int)(i & 255);
        int tok = g_rowtoken[row];
        uint4 o = make_uint4(0, 0, 0, 0);
        if (tok >= 0) {
            const float4* s = hs + (size_t)tok * (kD / 4) + 2 * q;
            float4 a = s[0], b = s[1];
            __half2 h0 = __floats2half2_rn(a.x, a.y), h1 = __floats2half2_rn(a.z, a.w);
            __half2 h2 = __floats2half2_rn(b.x, b.y), h3 = __floats2half2_rn(b.z, b.w);
            o.x = *(uint32_t*)&h0; o.y = *(uint32_t*)&h1;
            o.z = *(uint32_t*)&h2; o.w = *(uint32_t*)&h3;
        }
        ((uint4*)g_xperm)[i] = o;
    }
}

// ---------------- GEMM tile body ------------------------------------------
// CTA tile 128x128, 4 warps (2 M x 2 N), warp tile 64x64, occ 2.
// 3-stage cp.async pipeline, 1 barrier/chunk, tail-correct waits.
template <bool FIRST>
__device__ __forceinline__ void gemm_tile(int rt, int e, int xblk, uint32_t sb,
                                          float* __restrict__ out)
{
    constexpr int K = FIRST ? kD : kF;
    constexpr int NC = K / BK;
    const int rowbase = rt * TMm;
    const int colbase = xblk * TN;

    const int tid = threadIdx.x;
    const int warp = tid >> 5, lane = tid & 31;
    const int wm = warp & 1, wn = warp >> 1;   // 2 x 2 warps, 64x64 each

    const __half* Abase = FIRST ? g_xperm : g_h1h;
    const __half* Wb = (FIRST ? g_w1h : g_w2h) + (size_t)e * ((size_t)(FIRST ? kF : kD) * K);

    // ---- cp.async mapping: q = 16B group along K, r = base row (0..15) ----
    const int q = tid & 7, r = tid >> 3;
    const __half* aptr = Abase + (size_t)(rowbase + r) * K + q * 8;
    const __half* bptr = Wb + (size_t)(colbase + r) * K + q * 8;
    const uint32_t dA = (uint32_t)(r * 128 + ((q ^ (r & 7)) << 4));  // p*16 preserves row&7

    auto prefetch = [&](int c) {
        const uint32_t base = sb + (uint32_t)((c % ST) * STG);
        const __half* ap = aptr + c * BK;
#pragma unroll
        for (int p = 0; p < 8; p++)
            cp_async16(base + dA + (uint32_t)(p * 16 * 128), ap + (size_t)p * 16 * K);
        const __half* bp = bptr + c * BK;
#pragma unroll
        for (int p = 0; p < 8; p++)
            cp_async16(base + A_BYTES + dA + (uint32_t)(p * 16 * 128), bp + (size_t)p * 16 * K);
        asm volatile("cp.async.commit_group;" ::: "memory");
    };

    prefetch(0);
    prefetch(1);

    // ---- ldmatrix lane geometry ----
    const int rowA = wm * 64 + (lane & 15);
    const int kgA = lane >> 4;
    const int rowB = wn * 64 + ((lane >> 4) << 3) + (lane & 7);
    const int kgB = (lane >> 3) & 1;

    float acc[4][8][4];
#pragma unroll
    for (int i = 0; i < 4; i++)
#pragma unroll
        for (int j = 0; j < 8; j++)
#pragma unroll
            for (int v = 0; v < 4; v++) acc[i][j][v] = 0.f;

#pragma unroll 1
    for (int c = 0; c < NC; c++) {
        if (c < NC - 1) asm volatile("cp.async.wait_group 1;" ::: "memory");
        else            asm volatile("cp.async.wait_group 0;" ::: "memory");
        __syncthreads();
        if (c + 2 < NC) prefetch(c + 2);

        const uint32_t stA = sb + (uint32_t)((c % ST) * STG);
        const uint32_t stB = stA + A_BYTES;
#pragma unroll
        for (int s = 0; s < 4; s++) {
            uint32_t a[4][4];
#pragma unroll
            for (int mi = 0; mi < 4; mi++) {
                const int rr = rowA + mi * 16;
                ldsm_x4(a[mi], stA + (uint32_t)(rr * 128 + (((2 * s + kgA) ^ (rr & 7)) << 4)));
            }
            uint32_t b[4][4];
#pragma unroll
            for (int nj2 = 0; nj2 < 4; nj2++) {
                const int rr = rowB + nj2 * 16;
                ldsm_x4(b[nj2], stB + (uint32_t)(rr * 128 + (((2 * s + kgB) ^ (rr & 7)) << 4)));
            }
#pragma unroll
            for (int mi = 0; mi < 4; mi++)
#pragma unroll
                for (int nj = 0; nj < 8; nj++)
                    mma_f16(acc[mi][nj], a[mi], b[nj >> 1][(nj & 1) * 2], b[nj >> 1][(nj & 1) * 2 + 1]);
        }
    }

    // ---- epilogue ----
    const int g = lane >> 2, tig = lane & 3;
#pragma unroll
    for (int mi = 0; mi < 4; mi++) {
#pragma unroll
        for (int rr = 0; rr < 2; rr++) {
            const int lrow = rowbase + wm * 64 + mi * 16 + g + rr * 8;
            if (FIRST) {
                __half* hp = g_h1h + (size_t)lrow * kF + colbase;
#pragma unroll
                for (int nj = 0; nj < 8; nj++) {
                    const int col = wn * 64 + nj * 8 + tig * 2;
                    float v0 = acc[mi][nj][rr * 2 + 0];
                    float v1 = acc[mi][nj][rr * 2 + 1];
                    v0 = v0 / (1.f + __expf(-v0));       // SiLU
                    v1 = v1 / (1.f + __expf(-v1));
                    __half2 h = __floats2half2_rn(v0, v1);
                    *(uint32_t*)(hp + col) = *(uint32_t*)&h;
                }
            } else {
                const int tok = g_rowtoken[lrow];
                if (tok >= 0) {
                    float* op = out + (size_t)tok * kD + colbase;
#pragma unroll
                    for (int nj = 0; nj < 8; nj++) {
                        const int col = wn * 64 + nj * 8 + tig * 2;
                        float2 st;
                        st.x = acc[mi][nj][rr * 2 + 0];
                        st.y = acc[mi][nj][rr * 2 + 1];
                        *(float2*)(op + col) = st;
                    }
                }
            }
        }
    }
}

// ---------------- fused launch: [w2cvt || GEMM1] then GEMM2 ----------------
// flat ids: [0,1536): id%3==2 -> cvt slice id/3, else GEMM1 tile id-(id+1)/3
//           [1536,2816): GEMM1 tile id-512
//           [2816,3968): GEMM2 tile id-2816 (spin on cvt + per-rt GEMM1 done)
__global__ __launch_bounds__(NTH, 2) void k_moe(const float4* __restrict__ w2src,
                                                float* __restrict__ out)
{
    extern __shared__ char smem[];
    const uint32_t sb = smem_u32(smem);
    const int tid = threadIdx.x;
    const int id = blockIdx.x;

    if (id < PH1) {
        if (id < MIX && (id % 3) == 2) {
            // ---- w2 fp32->fp16 slice ----
            const long long base = (long long)(id / 3) * CVT_CHUNK;
            uint4* dst = (uint4*)g_w2h;
#pragma unroll 4
            for (int i = tid; i < CVT_CHUNK; i += NTH)
                cvt8(w2src + 2 * (size_t)(base + i), dst + base + i);
            __threadfence();
            __syncthreads();
            if (tid == 0) atomicAdd(&g_cvtdone, 1);
            return;
        }
        const int g1 = (id < MIX) ? (id - (id + 1) / 3) : (id - NCVT);
        const int rt = g1 >> 5, xblk = g1 & 31;
        const int e = g_tile_expert[rt];
        if (e >= 0) gemm_tile<true>(rt, e, xblk, sb, out);
        __threadfence();
        __syncthreads();
        if (tid == 0) atomicAdd(&g_done1[rt], 1);
    } else {
        const int g2 = id - PH1;
        const int rt = g2 >> 4, xblk = g2 & 15;
        const int e = g_tile_expert[rt];
        if (e < 0) return;
        if (tid == 0) {
            while (ld_acquire(&g_cvtdone) < NCVT) __nanosleep(128);
            while (ld_acquire(&g_done1[rt]) < XT1) __nanosleep(128);
        }
        __syncthreads();
        gemm_tile<false>(rt, e, xblk, sb, out);
    }
}

// ---------------- entry ----------------
extern "C" void kernel_launch(void* const* d_in, const int* in_sizes, int n_in,
                              void* d_out, int out_size) {
    const float* hs     = (const float*)d_in[0];
    const float* logits = (const float*)d_in[1];
    const float* w1     = (const float*)d_in[2];
    const float* w2     = (const float*)d_in[3];
    float* out = (float*)d_out;

    cudaFuncSetAttribute(k_moe, cudaFuncAttributeMaxDynamicSharedMemorySize, SMEM_BYTES);

    k_route<<<kT / 256, 256>>>(logits);
    k_offsets<<<1, 256>>>();
    k_scatter<<<kT / 256, 256>>>();
    k_prep<<<(unsigned)((W1_N8 + 255) / 256), 256>>>((const float4*)w1, (const float4*)hs);

    k_moe<<<TOTAL, NTH, SMEM_BYTES>>>((const float4*)w2, out);
}